// round 15
// baseline (speedup 1.0000x reference)
#include <cuda_runtime.h>
#include <cuda_fp16.h>
#include <math.h>
#include <stdint.h>

#define B_   2
#define T_   2048
#define D_   1024
#define H_   16
#define DH   64
#define WIN  128
#define M_   (B_*T_)          // 4096
#define SM_SCALE 0.125f

// ---------------- scratch ----------------
__device__ __align__(16) __half g_q[B_*H_*T_*DH];   // fp16(SM_SCALE * rope(q))
__device__ __align__(16) __half g_k[B_*H_*T_*DH];   // fp16(rope(k))
__device__ __align__(16) __half g_v[B_*H_*T_*DH];   // fp16(v)
__device__ __align__(16) __half g_ao[M_*D_];        // attn out (fp16)
__device__ __align__(16) __half g_qh[M_*D_];        // fp16 query
__device__ __align__(16) __half g_wh[4*D_*D_];      // fp16 Wq,Wk,Wv,Wo
__device__ __align__(16) float  g_cos[T_*32];
__device__ __align__(16) float  g_sin[T_*32];

// ---------------- helpers ----------------
__device__ __forceinline__ uint32_t smem_u32(const void* p) {
    uint32_t a;
    asm("{ .reg .u64 t; cvta.to.shared.u64 t, %1; cvt.u32.u64 %0, t; }" : "=r"(a) : "l"(p));
    return a;
}

#define CP_ASYNC16(dst, src) \
    asm volatile("cp.async.cg.shared.global [%0], [%1], 16;" :: "r"(dst), "l"(src))
#define CP_COMMIT() asm volatile("cp.async.commit_group;" ::: "memory")
#define CP_WAIT1()  asm volatile("cp.async.wait_group 1;"  ::: "memory")
#define CP_WAIT0()  asm volatile("cp.async.wait_group 0;"  ::: "memory")

__device__ __forceinline__ void ldsm4(unsigned &r0, unsigned &r1, unsigned &r2, unsigned &r3, uint32_t a) {
    asm volatile("ldmatrix.sync.aligned.m8n8.x4.shared.b16 {%0,%1,%2,%3}, [%4];"
        : "=r"(r0), "=r"(r1), "=r"(r2), "=r"(r3) : "r"(a));
}
__device__ __forceinline__ void ldsm4t(unsigned &r0, unsigned &r1, unsigned &r2, unsigned &r3, uint32_t a) {
    asm volatile("ldmatrix.sync.aligned.m8n8.x4.trans.shared.b16 {%0,%1,%2,%3}, [%4];"
        : "=r"(r0), "=r"(r1), "=r"(r2), "=r"(r3) : "r"(a));
}

__device__ __forceinline__ void mma_f16(float (&d)[4], const unsigned (&a)[4], const unsigned (&b)[2]) {
    asm volatile(
        "mma.sync.aligned.m16n8k16.row.col.f32.f16.f16.f32 "
        "{%0,%1,%2,%3}, {%4,%5,%6,%7}, {%8,%9}, {%0,%1,%2,%3};\n"
        : "+f"(d[0]), "+f"(d[1]), "+f"(d[2]), "+f"(d[3])
        : "r"(a[0]), "r"(a[1]), "r"(a[2]), "r"(a[3]), "r"(b[0]), "r"(b[1]));
}

__device__ __forceinline__ unsigned packh2(float a, float b) {
    __half2 h = __floats2half2_rn(a, b);
    return *(unsigned*)&h;
}

// ---------------- fused: fp16 pre-round + RoPE table ----------------
__global__ void round_rope_kernel(const float4* __restrict__ q, const float4* __restrict__ wq,
                                  const float4* __restrict__ wk, const float4* __restrict__ wv,
                                  const float4* __restrict__ wo) {
    int id = blockIdx.x*256 + threadIdx.x;
    const int WQ4 = D_*D_/4;
    if (id < T_*32) {
        int t = id >> 5, d = id & 31;
        float inv = (float)pow(10000.0, -(double)d/32.0);
        float a = (float)t * inv;
        float sv, cv;
        sincosf(a, &sv, &cv);
        g_cos[id] = cv;
        g_sin[id] = sv;
    }
    if (id < M_*D_/4) {
        float4 v = q[id];
        *(__half2*)(g_qh + id*4)     = __floats2half2_rn(v.x, v.y);
        *(__half2*)(g_qh + id*4 + 2) = __floats2half2_rn(v.z, v.w);
    }
    if (id < WQ4) {
        float4 v0 = wq[id], v1 = wk[id], v2 = wv[id], v3 = wo[id];
        *(__half2*)(g_wh + id*4)              = __floats2half2_rn(v0.x, v0.y);
        *(__half2*)(g_wh + id*4 + 2)          = __floats2half2_rn(v0.z, v0.w);
        *(__half2*)(g_wh + (size_t)WQ4*4  + id*4)     = __floats2half2_rn(v1.x, v1.y);
        *(__half2*)(g_wh + (size_t)WQ4*4  + id*4 + 2) = __floats2half2_rn(v1.z, v1.w);
        *(__half2*)(g_wh + (size_t)WQ4*8  + id*4)     = __floats2half2_rn(v2.x, v2.y);
        *(__half2*)(g_wh + (size_t)WQ4*8  + id*4 + 2) = __floats2half2_rn(v2.z, v2.w);
        *(__half2*)(g_wh + (size_t)WQ4*12 + id*4)     = __floats2half2_rn(v3.x, v3.y);
        *(__half2*)(g_wh + (size_t)WQ4*12 + id*4 + 2) = __floats2half2_rn(v3.z, v3.w);
    }
}

// ---------------- fp16 GEMM: BM=128 BN=64, 8 warps x (16 rows x 64 cols), 3 CTA/SM ----------------
#define GBM 128
#define GBN 64
#define GBK 64
#define NSTG 2
#define NCH  (D_/GBK)                 // 16
#define SRB  144                      // smem row bytes (128 data + 16 pad)
#define STG_BYTES ((GBM+GBN)*SRB)     // 27648
#define SMEM_TOT (NSTG*STG_BYTES)     // 55296

__device__ __forceinline__ void load_stage(uint32_t stg_b, const __half* __restrict__ Aq,
                                           const __half* __restrict__ Wm,
                                           int m0, int n0, int k0, int tid) {
    // A: 128 rows x 8 chunks = 1024 -> 4 each
    #pragma unroll
    for (int i = 0; i < 4; i++) {
        int id = tid + i*256;
        int row = id >> 3, ch = id & 7;
        uint32_t dst = stg_b + (uint32_t)(row*SRB + ch*16);
        CP_ASYNC16(dst, Aq + (size_t)(m0+row)*D_ + k0 + ch*8);
    }
    // B: 64 rows x 8 chunks = 512 -> 2 each
    uint32_t bb = stg_b + GBM*SRB;
    #pragma unroll
    for (int i = 0; i < 2; i++) {
        int id = tid + i*256;
        int row = id >> 3, ch = id & 7;
        uint32_t dst = bb + (uint32_t)(row*SRB + ch*16);
        CP_ASYNC16(dst, Wm + (size_t)(n0+row)*D_ + k0 + ch*8);
    }
}

template<int MODE>
__global__ void __launch_bounds__(256, 3) gemm_kernel(const float* __restrict__ bias,
                                                      float* __restrict__ out) {
    extern __shared__ __align__(16) unsigned smem[];
    uint32_t sb = smem_u32(smem);

    const int tid  = threadIdx.x;
    const int lane = tid & 31;
    const int warp = tid >> 5;          // 8 warps, each 16 rows x 64 cols
    const int g    = lane >> 2;
    const int tg   = lane & 3;
    const int w16  = warp << 4;

    const int rowA  = w16 + (lane & 7) + ((lane >> 3) & 1)*8;
    const int koffA = (lane >> 4)*16;
    const int rowB  = ((lane >> 4) << 3) + (lane & 7);
    const int koffB = ((lane >> 3) & 1)*16;

    const int m0   = blockIdx.y * GBM;
    const int nblk = blockIdx.x;

    int proj, n0;
    const __half *Aptr, *W;
    if (MODE == 0) {
        proj = nblk >> 4;  n0 = (nblk & 15) * GBN;
        Aptr = g_qh;  W = g_wh + (size_t)proj * D_ * D_;
    } else {
        proj = 3;  n0 = nblk * GBN;
        Aptr = g_ao;  W = g_wh + (size_t)3 * D_ * D_;
    }

    float acc[8][4];
    #pragma unroll
    for (int j = 0; j < 8; j++)
        #pragma unroll
        for (int k = 0; k < 4; k++) acc[j][k] = 0.f;

    load_stage(sb, Aptr, W, m0, n0, 0, tid);
    CP_COMMIT();

    for (int kt = 0; kt < NCH; kt++) {
        __syncthreads();                 // all warps done with buffer (kt+1)&1
        if (kt + 1 < NCH) {
            load_stage(sb + ((kt+1)&1)*STG_BYTES, Aptr, W, m0, n0, (kt+1)*GBK, tid);
            CP_COMMIT();
            CP_WAIT1();                  // stage kt ready
        } else {
            CP_WAIT0();
        }
        __syncthreads();                 // visibility

        const uint32_t stgb  = sb + (kt & 1)*STG_BYTES;
        const uint32_t abase = stgb + (uint32_t)(rowA*SRB + koffA);
        const uint32_t bbase = stgb + GBM*SRB + (uint32_t)(rowB*SRB + koffB);

        #pragma unroll
        for (int ks = 0; ks < 4; ks++) {
            unsigned af[4], bf[8][2];
            ldsm4(af[0], af[1], af[2], af[3], abase + ks*32);
            #pragma unroll
            for (int p = 0; p < 4; p++)
                ldsm4(bf[2*p][0], bf[2*p][1], bf[2*p+1][0], bf[2*p+1][1],
                      bbase + p*16*SRB + ks*32);
            #pragma unroll
            for (int nt = 0; nt < 8; nt++)
                mma_f16(acc[nt], af, bf[nt]);
        }
    }

    // -------- epilogue (warp covers rows w16..w16+16, cols n0..n0+64) --------
    #pragma unroll
    for (int half = 0; half < 2; half++) {
        int m = m0 + w16 + g + half*8;
        int t = m & (T_-1), bb = m >> 11;
        if (MODE == 0) {
            int h = n0 >> 6;
            if (proj < 2) {
                __half* rowh = &((proj == 0) ? g_q : g_k)[(((size_t)bb*H_ + h)*T_ + t)*DH];
                const float sc = (proj == 0) ? SM_SCALE : 1.0f;
                #pragma unroll
                for (int nt = 0; nt < 4; nt++) {
                    int d0 = nt*8 + 2*tg;
                    float2 cc = *(const float2*)&g_cos[t*32 + d0];
                    float2 ss = *(const float2*)&g_sin[t*32 + d0];
                    float x1a = acc[nt  ][half*2], x1b = acc[nt  ][half*2+1];
                    float x2a = acc[nt+4][half*2], x2b = acc[nt+4][half*2+1];
                    *(__half2*)&rowh[d0]      = __floats2half2_rn(sc*(x1a*cc.x - x2a*ss.x),
                                                                  sc*(x1b*cc.y - x2b*ss.y));
                    *(__half2*)&rowh[d0 + 32] = __floats2half2_rn(sc*(x2a*cc.x + x1a*ss.x),
                                                                  sc*(x2b*cc.y + x1b*ss.y));
                }
            } else {
                __half* rowh = &g_v[(((size_t)bb*H_ + h)*T_ + t)*DH];
                #pragma unroll
                for (int nt = 0; nt < 8; nt++) {
                    int d0 = nt*8 + 2*tg;
                    *(__half2*)&rowh[d0] = __floats2half2_rn(acc[nt][half*2],
                                                             acc[nt][half*2+1]);
                }
            }
        } else {
            float* orow = &out[(size_t)m*D_ + n0];
            #pragma unroll
            for (int nt = 0; nt < 8; nt++) {
                int nl = nt*8 + 2*tg;
                *(float2*)&orow[nl] = make_float2(acc[nt][half*2]   + bias[n0+nl],
                                                  acc[nt][half*2+1] + bias[n0+nl+1]);
            }
        }
    }
}

// ---------------- sliding-window attention (round-12 proven) ----------------
#define ARB 144                        // smem row bytes (72 halves)
#define CHB (64*ARB)                   // one K or V buffer = 9216 B
#define ATTN_SMEM (4*CHB)              // K0 V0 K1 V1 = 36864 B

__global__ void __launch_bounds__(128) attn_kernel() {
    extern __shared__ __align__(16) __half smemA[];
    const uint32_t sA = smem_u32(smemA);

    const int tid  = threadIdx.x;
    const int lane = tid & 31;
    const int warp = tid >> 5;
    const int g    = lane >> 2;
    const int t4   = lane & 3;

    const int b = blockIdx.z, h = blockIdx.y, qt = blockIdx.x;
    const int qstart = qt << 6;
    const int w16 = warp << 4;
    const int r0 = qstart + w16 + g;
    const int r1 = r0 + 8;
    const size_t bhrow = (size_t)(b*H_ + h)*T_;

    const int rowBk  = ((lane >> 4) << 3) + (lane & 7);
    const int koffBk = ((lane >> 3) & 1)*16;
    const uint32_t boffV = (uint32_t)((((lane >> 3) & 1)*8 + (lane & 7))*ARB + (lane >> 4)*16);

    unsigned qf[4][4];
    {
        const unsigned* qw = (const unsigned*)g_q;
        size_t rb0 = (bhrow + qstart + w16 + g)*32;
        size_t rb1 = rb0 + 8*32;
        #pragma unroll
        for (int ks = 0; ks < 4; ks++) {
            int kb = ks*8;
            qf[ks][0] = qw[rb0 + kb + t4];
            qf[ks][1] = qw[rb1 + kb + t4];
            qf[ks][2] = qw[rb0 + kb + t4 + 4];
            qf[ks][3] = qw[rb1 + kb + t4 + 4];
        }
    }

    float o[8][4];
    #pragma unroll
    for (int nt = 0; nt < 8; nt++)
        #pragma unroll
        for (int c = 0; c < 4; c++) o[nt][c] = 0.f;
    float m0v = -1e30f, m1v = -1e30f, l0 = 0.f, l1 = 0.f;

    const int nch = (qt < 2 ? qt : 2) + 1;
    const int clo = qt + 1 - nch;

    auto loadKV = [&](int ck, int bsel) {
        const int kstart = ck << 6;
        uint32_t kb = sA + (uint32_t)bsel*2*CHB;
        uint32_t vb = kb + CHB;
        #pragma unroll
        for (int j = 0; j < 4; j++) {
            int id = tid + j*128;
            int pos = id >> 3, ch = id & 7;
            size_t src = (bhrow + kstart + pos)*DH + ch*8;
            CP_ASYNC16(kb + (uint32_t)(pos*ARB + ch*16), g_k + src);
            CP_ASYNC16(vb + (uint32_t)(pos*ARB + ch*16), g_v + src);
        }
    };

    auto body = [&](int kstart, int bsel, int MODE) {
        uint32_t kbuf = sA + (uint32_t)bsel*2*CHB;
        uint32_t vbuf = kbuf + CHB;

        float s[8][4];
        #pragma unroll
        for (int nt = 0; nt < 8; nt++)
            #pragma unroll
            for (int c = 0; c < 4; c++) s[nt][c] = 0.f;
        #pragma unroll
        for (int ks = 0; ks < 4; ks++) {
            unsigned bf[8][2];
            #pragma unroll
            for (int p = 0; p < 4; p++)
                ldsm4(bf[2*p][0], bf[2*p][1], bf[2*p+1][0], bf[2*p+1][1],
                      kbuf + (uint32_t)((p*16 + rowBk)*ARB + ks*32 + koffBk));
            #pragma unroll
            for (int nt = 0; nt < 8; nt++)
                mma_f16(s[nt], qf[ks], bf[nt]);
        }

        const float NINF = -INFINITY;
        if (MODE == 0) {
            #pragma unroll
            for (int nt = 0; nt < 8; nt++) {
                int j0 = kstart + nt*8 + 2*t4;
                if (j0   < r0 - (WIN-1)) s[nt][0] = NINF;
                if (j0+1 < r0 - (WIN-1)) s[nt][1] = NINF;
                if (j0   < r1 - (WIN-1)) s[nt][2] = NINF;
                if (j0+1 < r1 - (WIN-1)) s[nt][3] = NINF;
            }
        } else if (MODE == 2) {
            #pragma unroll
            for (int nt = 0; nt < 8; nt++) {
                int j0 = kstart + nt*8 + 2*t4;
                if (j0   > r0) s[nt][0] = NINF;
                if (j0+1 > r0) s[nt][1] = NINF;
                if (j0   > r1) s[nt][2] = NINF;
                if (j0+1 > r1) s[nt][3] = NINF;
            }
        }

        float mx0 = NINF, mx1 = NINF;
        #pragma unroll
        for (int nt = 0; nt < 8; nt++) {
            mx0 = fmaxf(mx0, fmaxf(s[nt][0], s[nt][1]));
            mx1 = fmaxf(mx1, fmaxf(s[nt][2], s[nt][3]));
        }
        mx0 = fmaxf(mx0, __shfl_xor_sync(0xffffffffu, mx0, 1));
        mx0 = fmaxf(mx0, __shfl_xor_sync(0xffffffffu, mx0, 2));
        mx1 = fmaxf(mx1, __shfl_xor_sync(0xffffffffu, mx1, 1));
        mx1 = fmaxf(mx1, __shfl_xor_sync(0xffffffffu, mx1, 2));

        float mn0 = fmaxf(m0v, mx0), mn1 = fmaxf(m1v, mx1);
        float c0 = __expf(m0v - mn0), c1 = __expf(m1v - mn1);
        float rs0 = 0.f, rs1 = 0.f;
        #pragma unroll
        for (int nt = 0; nt < 8; nt++) {
            s[nt][0] = __expf(s[nt][0] - mn0);
            s[nt][1] = __expf(s[nt][1] - mn0);
            s[nt][2] = __expf(s[nt][2] - mn1);
            s[nt][3] = __expf(s[nt][3] - mn1);
            rs0 += s[nt][0] + s[nt][1];
            rs1 += s[nt][2] + s[nt][3];
        }
        rs0 += __shfl_xor_sync(0xffffffffu, rs0, 1);
        rs0 += __shfl_xor_sync(0xffffffffu, rs0, 2);
        rs1 += __shfl_xor_sync(0xffffffffu, rs1, 1);
        rs1 += __shfl_xor_sync(0xffffffffu, rs1, 2);
        l0 = l0*c0 + rs0;  l1 = l1*c1 + rs1;
        m0v = mn0;         m1v = mn1;
        #pragma unroll
        for (int nt = 0; nt < 8; nt++) {
            o[nt][0] *= c0; o[nt][1] *= c0;
            o[nt][2] *= c1; o[nt][3] *= c1;
        }

        #pragma unroll
        for (int ks = 0; ks < 4; ks++) {
            unsigned pa[4];
            pa[0] = packh2(s[2*ks  ][0], s[2*ks  ][1]);
            pa[1] = packh2(s[2*ks  ][2], s[2*ks  ][3]);
            pa[2] = packh2(s[2*ks+1][0], s[2*ks+1][1]);
            pa[3] = packh2(s[2*ks+1][2], s[2*ks+1][3]);
            #pragma unroll
            for (int p = 0; p < 4; p++) {
                unsigned vb4[4];
                ldsm4t(vb4[0], vb4[1], vb4[2], vb4[3],
                       vbuf + boffV + (uint32_t)(ks*16*ARB + p*32));
                unsigned b0[2] = {vb4[0], vb4[1]};
                unsigned b1[2] = {vb4[2], vb4[3]};
                mma_f16(o[2*p],   pa, b0);
                mma_f16(o[2*p+1], pa, b1);
            }
        }
    };

    loadKV(clo, 0);
    CP_COMMIT();
    for (int i = 0; i < nch; i++) {
        const int ck = clo + i;
        __syncthreads();
        if (i + 1 < nch) {
            loadKV(ck + 1, (i + 1) & 1);
            CP_COMMIT();
            CP_WAIT1();
        } else {
            CP_WAIT0();
        }
        __syncthreads();

        const int kstart = ck << 6;
        if (ck == qt)          body(kstart, i & 1, 2);
        else if (ck == qt - 1) body(kstart, i & 1, 1);
        else                   body(kstart, i & 1, 0);
    }

    const float inv0 = 1.0f / l0, inv1 = 1.0f / l1;
    __half* out0 = &g_ao[(size_t)(b*T_ + r0)*D_ + h*DH];
    __half* out1 = &g_ao[(size_t)(b*T_ + r1)*D_ + h*DH];
    #pragma unroll
    for (int nt = 0; nt < 8; nt++) {
        int d = nt*8 + 2*t4;
        *(__half2*)&out0[d] = __floats2half2_rn(o[nt][0]*inv0, o[nt][1]*inv0);
        *(__half2*)&out1[d] = __floats2half2_rn(o[nt][2]*inv1, o[nt][3]*inv1);
    }
}

// ---------------- launch ----------------
extern "C" void kernel_launch(void* const* d_in, const int* in_sizes, int n_in,
                              void* d_out, int out_size) {
    const float* query = (const float*)d_in[0];
    const float* Wq    = (const float*)d_in[1];
    const float* Wk    = (const float*)d_in[2];
    const float* Wv    = (const float*)d_in[3];
    const float* Wo    = (const float*)d_in[4];
    const float* bo    = (const float*)d_in[5];
    float* out = (float*)d_out;

    static int attr_done = 0;
    if (!attr_done) {
        cudaFuncSetAttribute(gemm_kernel<0>, cudaFuncAttributeMaxDynamicSharedMemorySize, SMEM_TOT);
        cudaFuncSetAttribute(gemm_kernel<1>, cudaFuncAttributeMaxDynamicSharedMemorySize, SMEM_TOT);
        cudaFuncSetAttribute(attn_kernel,   cudaFuncAttributeMaxDynamicSharedMemorySize, ATTN_SMEM);
        attr_done = 1;
    }

    round_rope_kernel<<<(M_*D_/4 + 255)/256, 256>>>((const float4*)query, (const float4*)Wq,
                                                    (const float4*)Wk, (const float4*)Wv,
                                                    (const float4*)Wo);
    gemm_kernel<0><<<dim3(48, M_/GBM), 256, SMEM_TOT>>>(nullptr, nullptr);
    attn_kernel<<<dim3(T_/64, H_, B_), 128, ATTN_SMEM>>>();
    gemm_kernel<1><<<dim3(16, M_/GBM), 256, SMEM_TOT>>>(bo, out);
}

// round 16
// speedup vs baseline: 1.1478x; 1.1478x over previous
#include <cuda_runtime.h>
#include <cuda_fp16.h>
#include <math.h>
#include <stdint.h>

#define B_   2
#define T_   2048
#define D_   1024
#define H_   16
#define DH   64
#define WIN  128
#define M_   (B_*T_)          // 4096
#define SM_SCALE 0.125f
#define LOG2E 1.4426950408889634f

// ---------------- scratch ----------------
__device__ __align__(16) __half g_q[B_*H_*T_*DH];   // fp16(SM_SCALE*log2e * rope(q))
__device__ __align__(16) __half g_k[B_*H_*T_*DH];   // fp16(rope(k))
__device__ __align__(16) __half g_v[B_*H_*T_*DH];   // fp16(v)
__device__ __align__(16) __half g_ao[M_*D_];        // attn out (fp16)
__device__ __align__(16) __half g_qh[M_*D_];        // fp16 query
__device__ __align__(16) __half g_wh[4*D_*D_];      // fp16 Wq,Wk,Wv,Wo
__device__ __align__(16) float  g_cos[T_*32];
__device__ __align__(16) float  g_sin[T_*32];

// ---------------- helpers ----------------
__device__ __forceinline__ uint32_t smem_u32(const void* p) {
    uint32_t a;
    asm("{ .reg .u64 t; cvta.to.shared.u64 t, %1; cvt.u32.u64 %0, t; }" : "=r"(a) : "l"(p));
    return a;
}

#define CP_ASYNC16(dst, src) \
    asm volatile("cp.async.cg.shared.global [%0], [%1], 16;" :: "r"(dst), "l"(src))
#define CP_COMMIT() asm volatile("cp.async.commit_group;" ::: "memory")
#define CP_WAIT1()  asm volatile("cp.async.wait_group 1;"  ::: "memory")
#define CP_WAIT0()  asm volatile("cp.async.wait_group 0;"  ::: "memory")

__device__ __forceinline__ void ldsm4(unsigned &r0, unsigned &r1, unsigned &r2, unsigned &r3, uint32_t a) {
    asm volatile("ldmatrix.sync.aligned.m8n8.x4.shared.b16 {%0,%1,%2,%3}, [%4];"
        : "=r"(r0), "=r"(r1), "=r"(r2), "=r"(r3) : "r"(a));
}
__device__ __forceinline__ void ldsm4t(unsigned &r0, unsigned &r1, unsigned &r2, unsigned &r3, uint32_t a) {
    asm volatile("ldmatrix.sync.aligned.m8n8.x4.trans.shared.b16 {%0,%1,%2,%3}, [%4];"
        : "=r"(r0), "=r"(r1), "=r"(r2), "=r"(r3) : "r"(a));
}

__device__ __forceinline__ void mma_f16(float (&d)[4], const unsigned (&a)[4], const unsigned (&b)[2]) {
    asm volatile(
        "mma.sync.aligned.m16n8k16.row.col.f32.f16.f16.f32 "
        "{%0,%1,%2,%3}, {%4,%5,%6,%7}, {%8,%9}, {%0,%1,%2,%3};\n"
        : "+f"(d[0]), "+f"(d[1]), "+f"(d[2]), "+f"(d[3])
        : "r"(a[0]), "r"(a[1]), "r"(a[2]), "r"(a[3]), "r"(b[0]), "r"(b[1]));
}

__device__ __forceinline__ unsigned packh2(float a, float b) {
    __half2 h = __floats2half2_rn(a, b);
    return *(unsigned*)&h;
}

// ---------------- fused: fp16 pre-round + RoPE table ----------------
__global__ void round_rope_kernel(const float4* __restrict__ q, const float4* __restrict__ wq,
                                  const float4* __restrict__ wk, const float4* __restrict__ wv,
                                  const float4* __restrict__ wo) {
    int id = blockIdx.x*256 + threadIdx.x;
    const int WQ4 = D_*D_/4;
    if (id < T_*32) {
        int t = id >> 5, d = id & 31;
        float inv = (float)pow(10000.0, -(double)d/32.0);
        float a = (float)t * inv;
        float sv, cv;
        sincosf(a, &sv, &cv);
        g_cos[id] = cv;
        g_sin[id] = sv;
    }
    if (id < M_*D_/4) {
        float4 v = q[id];
        *(__half2*)(g_qh + id*4)     = __floats2half2_rn(v.x, v.y);
        *(__half2*)(g_qh + id*4 + 2) = __floats2half2_rn(v.z, v.w);
    }
    if (id < WQ4) {
        float4 v0 = wq[id], v1 = wk[id], v2 = wv[id], v3 = wo[id];
        *(__half2*)(g_wh + id*4)              = __floats2half2_rn(v0.x, v0.y);
        *(__half2*)(g_wh + id*4 + 2)          = __floats2half2_rn(v0.z, v0.w);
        *(__half2*)(g_wh + (size_t)WQ4*4  + id*4)     = __floats2half2_rn(v1.x, v1.y);
        *(__half2*)(g_wh + (size_t)WQ4*4  + id*4 + 2) = __floats2half2_rn(v1.z, v1.w);
        *(__half2*)(g_wh + (size_t)WQ4*8  + id*4)     = __floats2half2_rn(v2.x, v2.y);
        *(__half2*)(g_wh + (size_t)WQ4*8  + id*4 + 2) = __floats2half2_rn(v2.z, v2.w);
        *(__half2*)(g_wh + (size_t)WQ4*12 + id*4)     = __floats2half2_rn(v3.x, v3.y);
        *(__half2*)(g_wh + (size_t)WQ4*12 + id*4 + 2) = __floats2half2_rn(v3.z, v3.w);
    }
}

// ---------------- fp16 cp.async 3-stage GEMM (round-14 proven shape) ----------------
#define GBM 128
#define GBN 128
#define GBK 64
#define NSTG 3
#define NCH  (D_/GBK)                 // 16
#define SRB  144
#define STG_BYTES (2*GBM*SRB)         // 36864
#define SMEM_TOT (NSTG*STG_BYTES)     // 110592

__device__ __forceinline__ void load_stage(uint32_t stg_b, const __half* __restrict__ Aq,
                                           const __half* __restrict__ Wm,
                                           int m0, int n0, int k0, int tid) {
    #pragma unroll
    for (int i = 0; i < 4; i++) {
        int id = tid + i*256;
        int row = id >> 3, ch = id & 7;
        uint32_t dst = stg_b + (uint32_t)(row*SRB + ch*16);
        CP_ASYNC16(dst, Aq + (size_t)(m0+row)*D_ + k0 + ch*8);
    }
    uint32_t bb = stg_b + GBM*SRB;
    #pragma unroll
    for (int i = 0; i < 4; i++) {
        int id = tid + i*256;
        int row = id >> 3, ch = id & 7;
        uint32_t dst = bb + (uint32_t)(row*SRB + ch*16);
        CP_ASYNC16(dst, Wm + (size_t)(n0+row)*D_ + k0 + ch*8);
    }
}

template<int MODE>
__global__ void __launch_bounds__(256, 2) gemm_kernel(const float* __restrict__ bias,
                                                      float* __restrict__ out) {
    extern __shared__ __align__(16) unsigned smem[];
    uint32_t sb = smem_u32(smem);

    const int tid  = threadIdx.x;
    const int lane = tid & 31;
    const int warp = tid >> 5;
    const int wm   = warp & 3;
    const int wn   = warp >> 2;
    const int g    = lane >> 2;
    const int tg   = lane & 3;

    const int rowA  = wm*32 + (lane & 7) + ((lane >> 3) & 1)*8;
    const int koffA = (lane >> 4)*16;
    const int rowB  = wn*64 + ((lane >> 4) << 3) + (lane & 7);
    const int koffB = ((lane >> 3) & 1)*16;

    const int m0   = blockIdx.y * GBM;
    const int nblk = blockIdx.x;

    int proj, n0;
    const __half *Aptr, *W;
    if (MODE == 0) {
        proj = nblk >> 3;  n0 = (nblk & 7) * GBN;
        Aptr = g_qh;  W = g_wh + (size_t)proj * D_ * D_;
    } else {
        proj = 3;  n0 = nblk * GBN;
        Aptr = g_ao;  W = g_wh + (size_t)3 * D_ * D_;
    }

    float acc[2][8][4];
    #pragma unroll
    for (int i = 0; i < 2; i++)
        #pragma unroll
        for (int j = 0; j < 8; j++)
            #pragma unroll
            for (int k = 0; k < 4; k++) acc[i][j][k] = 0.f;

    load_stage(sb,             Aptr, W, m0, n0, 0,   tid); CP_COMMIT();
    load_stage(sb + STG_BYTES, Aptr, W, m0, n0, GBK, tid); CP_COMMIT();

    for (int kt = 0; kt < NCH; kt++) {
        CP_WAIT1();
        __syncthreads();
        const int c2 = kt + NSTG - 1;
        if (c2 < NCH) {
            int s2 = c2 % NSTG;
            load_stage(sb + s2*STG_BYTES, Aptr, W, m0, n0, c2*GBK, tid);
        }
        CP_COMMIT();

        const uint32_t stgb  = sb + (kt % NSTG)*STG_BYTES;
        const uint32_t abase = stgb + (uint32_t)(rowA*SRB + koffA);
        const uint32_t bbase = stgb + GBM*SRB + (uint32_t)(rowB*SRB + koffB);

        #pragma unroll
        for (int ks = 0; ks < 4; ks++) {
            unsigned af[2][4], bf[8][2];
            ldsm4(af[0][0], af[0][1], af[0][2], af[0][3], abase + ks*32);
            ldsm4(af[1][0], af[1][1], af[1][2], af[1][3], abase + 16*SRB + ks*32);
            #pragma unroll
            for (int p = 0; p < 4; p++)
                ldsm4(bf[2*p][0], bf[2*p][1], bf[2*p+1][0], bf[2*p+1][1],
                      bbase + p*16*SRB + ks*32);
            #pragma unroll
            for (int mt = 0; mt < 2; mt++)
                #pragma unroll
                for (int nt = 0; nt < 8; nt++)
                    mma_f16(acc[mt][nt], af[mt], bf[nt]);
        }
    }

    // -------- epilogue --------
    #pragma unroll
    for (int mt = 0; mt < 2; mt++) {
        #pragma unroll
        for (int half = 0; half < 2; half++) {
            int m = m0 + wm*32 + mt*16 + g + half*8;
            int t = m & (T_-1), bb = m >> 11;
            if (MODE == 0) {
                int h = (n0 + wn*64) >> 6;
                if (proj < 2) {
                    __half* rowh = &((proj == 0) ? g_q : g_k)[(((size_t)bb*H_ + h)*T_ + t)*DH];
                    // q carries SM_SCALE * log2e so softmax can use exp2
                    const float sc = (proj == 0) ? (SM_SCALE * LOG2E) : 1.0f;
                    #pragma unroll
                    for (int nt = 0; nt < 4; nt++) {
                        int d0 = nt*8 + 2*tg;
                        float2 cc = *(const float2*)&g_cos[t*32 + d0];
                        float2 ss = *(const float2*)&g_sin[t*32 + d0];
                        float x1a = acc[mt][nt  ][half*2], x1b = acc[mt][nt  ][half*2+1];
                        float x2a = acc[mt][nt+4][half*2], x2b = acc[mt][nt+4][half*2+1];
                        *(__half2*)&rowh[d0]      = __floats2half2_rn(sc*(x1a*cc.x - x2a*ss.x),
                                                                      sc*(x1b*cc.y - x2b*ss.y));
                        *(__half2*)&rowh[d0 + 32] = __floats2half2_rn(sc*(x2a*cc.x + x1a*ss.x),
                                                                      sc*(x2b*cc.y + x1b*ss.y));
                    }
                } else {
                    __half* rowh = &g_v[(((size_t)bb*H_ + h)*T_ + t)*DH];
                    #pragma unroll
                    for (int nt = 0; nt < 8; nt++) {
                        int d0 = nt*8 + 2*tg;
                        *(__half2*)&rowh[d0] = __floats2half2_rn(acc[mt][nt][half*2],
                                                                 acc[mt][nt][half*2+1]);
                    }
                }
            } else {
                int ncol = n0 + wn*64;
                float* orow = &out[(size_t)m*D_ + ncol];
                #pragma unroll
                for (int nt = 0; nt < 8; nt++) {
                    int nl = nt*8 + 2*tg;
                    *(float2*)&orow[nl] = make_float2(acc[mt][nt][half*2]   + bias[ncol+nl],
                                                      acc[mt][nt][half*2+1] + bias[ncol+nl+1]);
                }
            }
        }
    }
}

// ---------------- sliding-window attention (round-12 proven, exp2 softmax) ----------------
#define ARB 144                        // smem row bytes (72 halves)
#define CHB (64*ARB)                   // one K or V buffer = 9216 B
#define ATTN_SMEM (4*CHB)              // K0 V0 K1 V1 = 36864 B

__global__ void __launch_bounds__(128) attn_kernel() {
    extern __shared__ __align__(16) __half smemA[];
    const uint32_t sA = smem_u32(smemA);

    const int tid  = threadIdx.x;
    const int lane = tid & 31;
    const int warp = tid >> 5;
    const int g    = lane >> 2;
    const int t4   = lane & 3;

    const int b = blockIdx.z, h = blockIdx.y, qt = blockIdx.x;
    const int qstart = qt << 6;
    const int w16 = warp << 4;
    const int r0 = qstart + w16 + g;
    const int r1 = r0 + 8;
    const size_t bhrow = (size_t)(b*H_ + h)*T_;

    const int rowBk  = ((lane >> 4) << 3) + (lane & 7);
    const int koffBk = ((lane >> 3) & 1)*16;
    const uint32_t boffV = (uint32_t)((((lane >> 3) & 1)*8 + (lane & 7))*ARB + (lane >> 4)*16);

    unsigned qf[4][4];
    {
        const unsigned* qw = (const unsigned*)g_q;
        size_t rb0 = (bhrow + qstart + w16 + g)*32;
        size_t rb1 = rb0 + 8*32;
        #pragma unroll
        for (int ks = 0; ks < 4; ks++) {
            int kb = ks*8;
            qf[ks][0] = qw[rb0 + kb + t4];
            qf[ks][1] = qw[rb1 + kb + t4];
            qf[ks][2] = qw[rb0 + kb + t4 + 4];
            qf[ks][3] = qw[rb1 + kb + t4 + 4];
        }
    }

    float o[8][4];
    #pragma unroll
    for (int nt = 0; nt < 8; nt++)
        #pragma unroll
        for (int c = 0; c < 4; c++) o[nt][c] = 0.f;
    float m0v = -1e30f, m1v = -1e30f, l0 = 0.f, l1 = 0.f;

    const int nch = (qt < 2 ? qt : 2) + 1;
    const int clo = qt + 1 - nch;

    auto loadKV = [&](int ck, int bsel) {
        const int kstart = ck << 6;
        uint32_t kb = sA + (uint32_t)bsel*2*CHB;
        uint32_t vb = kb + CHB;
        #pragma unroll
        for (int j = 0; j < 4; j++) {
            int id = tid + j*128;
            int pos = id >> 3, ch = id & 7;
            size_t src = (bhrow + kstart + pos)*DH + ch*8;
            CP_ASYNC16(kb + (uint32_t)(pos*ARB + ch*16), g_k + src);
            CP_ASYNC16(vb + (uint32_t)(pos*ARB + ch*16), g_v + src);
        }
    };

    // chunk body; MODE: 0 = window-only, 1 = no mask, 2 = causal-only
    auto body = [&](int kstart, int bsel, int MODE) {
        uint32_t kbuf = sA + (uint32_t)bsel*2*CHB;
        uint32_t vbuf = kbuf + CHB;

        float s[8][4];
        #pragma unroll
        for (int nt = 0; nt < 8; nt++)
            #pragma unroll
            for (int c = 0; c < 4; c++) s[nt][c] = 0.f;
        #pragma unroll
        for (int ks = 0; ks < 4; ks++) {
            unsigned bf[8][2];
            #pragma unroll
            for (int p = 0; p < 4; p++)
                ldsm4(bf[2*p][0], bf[2*p][1], bf[2*p+1][0], bf[2*p+1][1],
                      kbuf + (uint32_t)((p*16 + rowBk)*ARB + ks*32 + koffBk));
            #pragma unroll
            for (int nt = 0; nt < 8; nt++)
                mma_f16(s[nt], qf[ks], bf[nt]);
        }

        const float NINF = -INFINITY;
        if (MODE == 0) {
            #pragma unroll
            for (int nt = 0; nt < 8; nt++) {
                int j0 = kstart + nt*8 + 2*t4;
                if (j0   < r0 - (WIN-1)) s[nt][0] = NINF;
                if (j0+1 < r0 - (WIN-1)) s[nt][1] = NINF;
                if (j0   < r1 - (WIN-1)) s[nt][2] = NINF;
                if (j0+1 < r1 - (WIN-1)) s[nt][3] = NINF;
            }
        } else if (MODE == 2) {
            #pragma unroll
            for (int nt = 0; nt < 8; nt++) {
                int j0 = kstart + nt*8 + 2*t4;
                if (j0   > r0) s[nt][0] = NINF;
                if (j0+1 > r0) s[nt][1] = NINF;
                if (j0   > r1) s[nt][2] = NINF;
                if (j0+1 > r1) s[nt][3] = NINF;
            }
        }

        float mx0 = NINF, mx1 = NINF;
        #pragma unroll
        for (int nt = 0; nt < 8; nt++) {
            mx0 = fmaxf(mx0, fmaxf(s[nt][0], s[nt][1]));
            mx1 = fmaxf(mx1, fmaxf(s[nt][2], s[nt][3]));
        }
        mx0 = fmaxf(mx0, __shfl_xor_sync(0xffffffffu, mx0, 1));
        mx0 = fmaxf(mx0, __shfl_xor_sync(0xffffffffu, mx0, 2));
        mx1 = fmaxf(mx1, __shfl_xor_sync(0xffffffffu, mx1, 1));
        mx1 = fmaxf(mx1, __shfl_xor_sync(0xffffffffu, mx1, 2));

        float mn0 = fmaxf(m0v, mx0), mn1 = fmaxf(m1v, mx1);
        float c0 = exp2f(m0v - mn0), c1 = exp2f(m1v - mn1);
        float rs0 = 0.f, rs1 = 0.f;
        #pragma unroll
        for (int nt = 0; nt < 8; nt++) {
            s[nt][0] = exp2f(s[nt][0] - mn0);
            s[nt][1] = exp2f(s[nt][1] - mn0);
            s[nt][2] = exp2f(s[nt][2] - mn1);
            s[nt][3] = exp2f(s[nt][3] - mn1);
            rs0 += s[nt][0] + s[nt][1];
            rs1 += s[nt][2] + s[nt][3];
        }
        rs0 += __shfl_xor_sync(0xffffffffu, rs0, 1);
        rs0 += __shfl_xor_sync(0xffffffffu, rs0, 2);
        rs1 += __shfl_xor_sync(0xffffffffu, rs1, 1);
        rs1 += __shfl_xor_sync(0xffffffffu, rs1, 2);
        l0 = l0*c0 + rs0;  l1 = l1*c1 + rs1;
        m0v = mn0;         m1v = mn1;
        #pragma unroll
        for (int nt = 0; nt < 8; nt++) {
            o[nt][0] *= c0; o[nt][1] *= c0;
            o[nt][2] *= c1; o[nt][3] *= c1;
        }

        // O += P V : P a-fragments built directly from s registers (layout-exact)
        #pragma unroll
        for (int ks = 0; ks < 4; ks++) {
            unsigned pa[4];
            pa[0] = packh2(s[2*ks  ][0], s[2*ks  ][1]);
            pa[1] = packh2(s[2*ks  ][2], s[2*ks  ][3]);
            pa[2] = packh2(s[2*ks+1][0], s[2*ks+1][1]);
            pa[3] = packh2(s[2*ks+1][2], s[2*ks+1][3]);
            #pragma unroll
            for (int p = 0; p < 4; p++) {
                unsigned vb4[4];
                ldsm4t(vb4[0], vb4[1], vb4[2], vb4[3],
                       vbuf + boffV + (uint32_t)(ks*16*ARB + p*32));
                unsigned b0[2] = {vb4[0], vb4[1]};
                unsigned b1[2] = {vb4[2], vb4[3]};
                mma_f16(o[2*p],   pa, b0);
                mma_f16(o[2*p+1], pa, b1);
            }
        }
    };

    loadKV(clo, 0);
    CP_COMMIT();
    for (int i = 0; i < nch; i++) {
        const int ck = clo + i;
        __syncthreads();
        if (i + 1 < nch) {
            loadKV(ck + 1, (i + 1) & 1);
            CP_COMMIT();
            CP_WAIT1();
        } else {
            CP_WAIT0();
        }
        __syncthreads();

        const int kstart = ck << 6;
        if (ck == qt)          body(kstart, i & 1, 2);
        else if (ck == qt - 1) body(kstart, i & 1, 1);
        else                   body(kstart, i & 1, 0);
    }

    const float inv0 = 1.0f / l0, inv1 = 1.0f / l1;
    __half* out0 = &g_ao[(size_t)(b*T_ + r0)*D_ + h*DH];
    __half* out1 = &g_ao[(size_t)(b*T_ + r1)*D_ + h*DH];
    #pragma unroll
    for (int nt = 0; nt < 8; nt++) {
        int d = nt*8 + 2*t4;
        *(__half2*)&out0[d] = __floats2half2_rn(o[nt][0]*inv0, o[nt][1]*inv0);
        *(__half2*)&out1[d] = __floats2half2_rn(o[nt][2]*inv1, o[nt][3]*inv1);
    }
}

// ---------------- launch ----------------
extern "C" void kernel_launch(void* const* d_in, const int* in_sizes, int n_in,
                              void* d_out, int out_size) {
    const float* query = (const float*)d_in[0];
    const float* Wq    = (const float*)d_in[1];
    const float* Wk    = (const float*)d_in[2];
    const float* Wv    = (const float*)d_in[3];
    const float* Wo    = (const float*)d_in[4];
    const float* bo    = (const float*)d_in[5];
    float* out = (float*)d_out;

    static int attr_done = 0;
    if (!attr_done) {
        cudaFuncSetAttribute(gemm_kernel<0>, cudaFuncAttributeMaxDynamicSharedMemorySize, SMEM_TOT);
        cudaFuncSetAttribute(gemm_kernel<1>, cudaFuncAttributeMaxDynamicSharedMemorySize, SMEM_TOT);
        cudaFuncSetAttribute(attn_kernel,   cudaFuncAttributeMaxDynamicSharedMemorySize, ATTN_SMEM);
        attr_done = 1;
    }

    round_rope_kernel<<<(M_*D_/4 + 255)/256, 256>>>((const float4*)query, (const float4*)Wq,
                                                    (const float4*)Wk, (const float4*)Wv,
                                                    (const float4*)Wo);
    gemm_kernel<0><<<dim3(24, M_/GBM), 256, SMEM_TOT>>>(nullptr, nullptr);
    attn_kernel<<<dim3(T_/64, H_, B_), 128, ATTN_SMEM>>>();
    gemm_kernel<1><<<dim3(8, M_/GBM), 256, SMEM_TOT>>>(bo, out);
}